// round 1
// baseline (speedup 1.0000x reference)
#include <cuda_runtime.h>
#include <math.h>

#define T_LEN 176400
#define NBATCH 16
#define NHARM 64
#define NBANDS 65

// Scratch (no allocations allowed): per-batch params + per-batch max accumulator
__device__ float g_params[NBATCH * 12];
__device__ unsigned int g_max[NBATCH];

// exact double pi
#define PI_D 3.141592653589793115997963468544185161590576171875
// double 2*pi (exact double rounding of 2*pi)
#define TWOPI_D 6.28318530717958647692528676655900576839
#define INV2PI_D 0.159154943091895335768883763372514362096873

// ---------------------------------------------------------------------------
// Accurate sin of an f32 value (|arg| < ~2^20), matching libdevice-accurate
// sinf to ~2.5e-7 absolute. Immune to -use_fast_math.
// ---------------------------------------------------------------------------
__device__ __forceinline__ float sin_match(float arg) {
    double d = (double)arg;
    double qn = rint(d * INV2PI_D);
    double r = fma(qn, -TWOPI_D, d);         // r in [-pi, pi], abs err ~3e-11
    float rf = (float)r;
    int mi = __float2int_rn(rf * 0.63661977236758134308f); // round(r/(pi/2)) in {-2..2}
    float mf = (float)mi;
    float x = fmaf(mf, -1.57079637050628662109375f, rf);   // - m*PIO2_HI
    x = fmaf(mf, 4.37113900018624283e-8f, x);              // - m*PIO2_LO (LO<0)
    float z = x * x;
    // sin poly on [-pi/4, pi/4] (Cephes)
    float ps = fmaf(z, -1.9515295891e-4f, 8.3321608736e-3f);
    ps = fmaf(z, ps, -1.6666654611e-1f);
    float sinp = fmaf(x * z, ps, x);
    // cos poly on [-pi/4, pi/4] (Cephes)
    float pc = fmaf(z, 2.443315711809948e-5f, -1.388731625493765e-3f);
    pc = fmaf(z, pc, 4.166664568298827e-2f);
    float cosp = fmaf(z, fmaf(z, pc, -0.5f), 1.0f);
    float v = (mi & 1) ? cosp : sinp;
    return (mi & 2) ? -v : v;
}

// ---------------------------------------------------------------------------
// Kernel 1: per-batch parameter precompute (replicates _adsr_env int math),
// noise level, gain; zeroes max accumulators.
// ---------------------------------------------------------------------------
__global__ void ddsp_prep(const float* __restrict__ noise_bands,
                          const float* __restrict__ adsr,
                          const float* __restrict__ gain) {
    int b = threadIdx.x;
    if (b >= NBATCH) return;
    g_max[b] = 0u;

    // noise_level = mean(noise_bands)*0.1
    float s = 0.0f;
    for (int j = 0; j < NBANDS; j++) s += noise_bands[b * NBANDS + j];
    float nl = (s / (float)NBANDS) * 0.1f;

    float attack  = adsr[b * 4 + 0];
    float decay   = adsr[b * 4 + 1];
    float sus     = adsr[b * 4 + 2];
    float release = adsr[b * 4 + 3];

    // a = floor(attack*0.5*SR)+1  (f32 ops, left-assoc, matching jax)
    int a  = (int)floorf(__fmul_rn(__fmul_rn(attack,  0.5f), 44100.0f)) + 1;
    int dd = (int)floorf(__fmul_rn(__fmul_rn(decay,   0.5f), 44100.0f)) + 1;
    int rr = (int)floorf(__fmul_rn(__fmul_rn(release, 0.5f), 44100.0f)) + 1;
    int total = a + dd + rr;
    if (total > T_LEN) {
        float scale = __fdiv_rn((float)T_LEN, (float)total);
        a  = (int)floorf(__fmul_rn((float)a,  scale));
        dd = (int)floorf(__fmul_rn((float)dd, scale));
        rr = (int)floorf(__fmul_rn((float)rr, scale));
    }
    int ss = T_LEN - (a + dd + rr);
    if (ss < 0) ss = 0;

    float af = (float)a, df = (float)dd, sf = (float)ss, rf = (float)rr;
    float* P = g_params + b * 12;
    P[0] = af;                 // a
    P[1] = af + df;            // a+d  (exact, small ints)
    P[2] = af + df + sf;       // a+d+s
    P[3] = 1.0f / fmaxf(af - 1.0f, 1.0f);
    P[4] = 1.0f / fmaxf(df - 1.0f, 1.0f);
    P[5] = 1.0f / fmaxf(rf - 1.0f, 1.0f);
    P[6] = sus;
    P[7] = gain[b];
    P[8] = nl;
}

// ---------------------------------------------------------------------------
// Kernel 2: main fused kernel. One thread = one time sample i, all 16 batches.
// ---------------------------------------------------------------------------
__global__ void __launch_bounds__(256) ddsp_main(
    const float* __restrict__ hd,      // (16, 64)
    const float* __restrict__ noise,   // (16, T)
    float* __restrict__ out)           // (16, T)
{
    __shared__ float sh_hd[NHARM * 16];   // transposed: [k][b]
    __shared__ float sh_ck[NHARM];
    __shared__ float sh_par[NBATCH * 12];
    __shared__ unsigned int sh_max[NBATCH];

    int tid = threadIdx.x;
    for (int idx = tid; idx < NHARM * 16; idx += 256) {
        int k = idx >> 4, b = idx & 15;
        sh_hd[idx] = hd[b * NHARM + k];
    }
    if (tid < NHARM) {
        // ck = fl32( fl32(2*pi*440) * (k+1) )
        const float C32 = (float)(2.0 * PI_D * 440.0);
        sh_ck[tid] = __fmul_rn(C32, (float)(tid + 1));
    }
    if (tid < NBATCH * 12) sh_par[tid] = g_params[tid];
    if (tid < NBATCH) sh_max[tid] = 0u;
    __syncthreads();

    int i = blockIdx.x * 256 + tid;
    bool act = (i < T_LEN);
    float fi = (float)i;
    // t_i = fl32( i * fl32(4.0/176399.0) )   (jax linspace: start + iota*delta)
    const float DELTA = 4.0f / 176399.0f;   // compile-time IEEE f32
    float ti = __fmul_rn(fi, DELTA);

    float acc[16];
#pragma unroll
    for (int b = 0; b < 16; b++) acc[b] = 0.0f;

#pragma unroll 4
    for (int k = 0; k < NHARM; k++) {
        float arg = __fmul_rn(sh_ck[k], ti);   // matches ref f32 rounding
        float sv = sin_match(arg);
        const float4* hp = (const float4*)(sh_hd + k * 16);
        float4 h0 = hp[0], h1 = hp[1], h2 = hp[2], h3 = hp[3];
        acc[0]  = fmaf(h0.x, sv, acc[0]);  acc[1]  = fmaf(h0.y, sv, acc[1]);
        acc[2]  = fmaf(h0.z, sv, acc[2]);  acc[3]  = fmaf(h0.w, sv, acc[3]);
        acc[4]  = fmaf(h1.x, sv, acc[4]);  acc[5]  = fmaf(h1.y, sv, acc[5]);
        acc[6]  = fmaf(h1.z, sv, acc[6]);  acc[7]  = fmaf(h1.w, sv, acc[7]);
        acc[8]  = fmaf(h2.x, sv, acc[8]);  acc[9]  = fmaf(h2.y, sv, acc[9]);
        acc[10] = fmaf(h2.z, sv, acc[10]); acc[11] = fmaf(h2.w, sv, acc[11]);
        acc[12] = fmaf(h3.x, sv, acc[12]); acc[13] = fmaf(h3.y, sv, acc[13]);
        acc[14] = fmaf(h3.z, sv, acc[14]); acc[15] = fmaf(h3.w, sv, acc[15]);
    }

    const unsigned full = 0xFFFFFFFFu;
#pragma unroll
    for (int b = 0; b < 16; b++) {
        const float* P = sh_par + b * 12;
        float af = P[0], afd = P[1], ads = P[2];
        float ida = P[3], idd = P[4], idr = P[5];
        float sus = P[6], gn = P[7], nl = P[8];

        float env;
        if (fi < af)       env = fi * ida;
        else if (fi < afd) env = 1.0f + ((sus - 1.0f) * (fi - af)) * idd;
        else if (fi < ads) env = sus;
        else               env = sus * (1.0f - (fi - ads) * idr);

        float nz = act ? noise[b * T_LEN + i] : 0.0f;
        float nn = fmaf(nz, 2.0f, -1.0f) * nl;
        float sig = ((acc[b] + nn) * env) * gn;
        if (!act) sig = 0.0f;
        if (act) out[b * T_LEN + i] = sig;

        float am = fabsf(sig);
#pragma unroll
        for (int off = 16; off; off >>= 1)
            am = fmaxf(am, __shfl_xor_sync(full, am, off));
        if ((tid & 31) == 0) atomicMax(&sh_max[b], __float_as_uint(am));
    }
    __syncthreads();
    if (tid < NBATCH) atomicMax(&g_max[tid], sh_max[tid]);
}

// ---------------------------------------------------------------------------
// Kernel 3: normalize by per-batch max(|sig|)+1e-5
// ---------------------------------------------------------------------------
__global__ void ddsp_norm(float* __restrict__ out) {
    int i = blockIdx.x * 256 + threadIdx.x;
    int b = blockIdx.y;
    if (i < T_LEN) {
        float m = __uint_as_float(g_max[b]) + 1e-5f;
        int idx = b * T_LEN + i;
        out[idx] = out[idx] / m;
    }
}

extern "C" void kernel_launch(void* const* d_in, const int* in_sizes, int n_in,
                              void* d_out, int out_size) {
    // input order: base_audio, harmonic_dist, noise_bands, adsr, gain, noise
    const float* hd     = (const float*)d_in[1];
    const float* nbands = (const float*)d_in[2];
    const float* adsr   = (const float*)d_in[3];
    const float* gain   = (const float*)d_in[4];
    const float* noise  = (const float*)d_in[5];
    float* out = (float*)d_out;

    int grid = (T_LEN + 255) / 256;
    ddsp_prep<<<1, 32>>>(nbands, adsr, gain);
    ddsp_main<<<grid, 256>>>(hd, noise, out);
    ddsp_norm<<<dim3(grid, NBATCH), 256>>>(out);
}

// round 2
// speedup vs baseline: 3.7613x; 3.7613x over previous
#include <cuda_runtime.h>
#include <math.h>

#define T_LEN 176400
#define NBATCH 16
#define NHARM 64
#define NBANDS 65

// Scratch (no allocations allowed): per-batch params + per-batch max accumulator
__device__ float g_params[NBATCH * 12];
__device__ unsigned int g_max[NBATCH];

#define PI_D 3.141592653589793115997963468544185161590576171875

// ---------------------------------------------------------------------------
// All-FP32 accurate sin for |arg| < 2^20.
//  n = RNE(arg/2pi) via 1.5*2^23 magic (valid: |arg/2pi| < 112700 << 2^22)
//  2-term Cody-Waite with FMA (C1 = fl32(2pi), C2 = 2pi - C1 exact to f32)
//  odd Taylor poly through x^15 on [-pi,pi]  (abs err <= ~8e-7)
// 13 fma-pipe ops, no FP64, no MUFU, no branches.
// ---------------------------------------------------------------------------
__device__ __forceinline__ float sin_fast(float a) {
    const float I2PI  = 0.15915494309189535f;
    const float MAGIC = 12582912.0f;                // 1.5 * 2^23
    const float C1    = 6.28318548202514648437500f; // fl32(2*pi) = 0x40C90FDB
    const float C2N   = 1.7484556000744625e-7f;     // -(2*pi - C1)
    float t  = fmaf(a, I2PI, MAGIC);
    float nf = t - MAGIC;                           // RNE(a/2pi), exact int
    float r  = fmaf(nf, -C1, a);
    r = fmaf(nf, C2N, r);                           // r in ~[-pi, pi]
    float z = r * r;
    float p = -7.6471637318198164e-13f;             // -1/15!
    p = fmaf(p, z, 1.6059043836821613e-10f);        //  1/13!
    p = fmaf(p, z, -2.5052108385441720e-8f);        // -1/11!
    p = fmaf(p, z, 2.7557319223985893e-6f);         //  1/9!
    p = fmaf(p, z, -1.9841269841269841e-4f);        // -1/7!
    p = fmaf(p, z, 8.3333333333333332e-3f);         //  1/5!
    p = fmaf(p, z, -1.6666666666666666e-1f);        // -1/3!
    return fmaf(r * z, p, r);
}

// ---------------------------------------------------------------------------
// Kernel 1: per-batch parameter precompute (replicates _adsr_env int math),
// noise level, gain; zeroes max accumulators.
// ---------------------------------------------------------------------------
__global__ void ddsp_prep(const float* __restrict__ noise_bands,
                          const float* __restrict__ adsr,
                          const float* __restrict__ gain) {
    int b = threadIdx.x;
    if (b >= NBATCH) return;
    g_max[b] = 0u;

    float s = 0.0f;
    for (int j = 0; j < NBANDS; j++) s += noise_bands[b * NBANDS + j];
    float nl = (s / (float)NBANDS) * 0.1f;

    float attack  = adsr[b * 4 + 0];
    float decay   = adsr[b * 4 + 1];
    float sus     = adsr[b * 4 + 2];
    float release = adsr[b * 4 + 3];

    int a  = (int)floorf(__fmul_rn(__fmul_rn(attack,  0.5f), 44100.0f)) + 1;
    int dd = (int)floorf(__fmul_rn(__fmul_rn(decay,   0.5f), 44100.0f)) + 1;
    int rr = (int)floorf(__fmul_rn(__fmul_rn(release, 0.5f), 44100.0f)) + 1;
    int total = a + dd + rr;
    if (total > T_LEN) {
        float scale = __fdiv_rn((float)T_LEN, (float)total);
        a  = (int)floorf(__fmul_rn((float)a,  scale));
        dd = (int)floorf(__fmul_rn((float)dd, scale));
        rr = (int)floorf(__fmul_rn((float)rr, scale));
    }
    int ss = T_LEN - (a + dd + rr);
    if (ss < 0) ss = 0;

    float af = (float)a, df = (float)dd, sf = (float)ss, rf = (float)rr;
    float* P = g_params + b * 12;
    P[0] = af;
    P[1] = af + df;
    P[2] = af + df + sf;
    P[3] = 1.0f / fmaxf(af - 1.0f, 1.0f);
    P[4] = 1.0f / fmaxf(df - 1.0f, 1.0f);
    P[5] = 1.0f / fmaxf(rf - 1.0f, 1.0f);
    P[6] = sus;
    P[7] = gain[b];
    P[8] = nl;
}

// ---------------------------------------------------------------------------
// Kernel 2: main fused kernel. One thread = one time sample i, all 16 batches.
// ---------------------------------------------------------------------------
__global__ void __launch_bounds__(256) ddsp_main(
    const float* __restrict__ hd,      // (16, 64)
    const float* __restrict__ noise,   // (16, T)
    float* __restrict__ out)           // (16, T)
{
    __shared__ float sh_hd[NHARM * 16];   // transposed: [k][b]
    __shared__ float sh_ck[NHARM];
    __shared__ float sh_par[NBATCH * 12];
    __shared__ unsigned int sh_max[NBATCH];

    int tid = threadIdx.x;
    for (int idx = tid; idx < NHARM * 16; idx += 256) {
        int k = idx >> 4, b = idx & 15;
        sh_hd[idx] = hd[b * NHARM + k];
    }
    if (tid < NHARM) {
        const float C32 = (float)(2.0 * PI_D * 440.0);   // fl32(2*pi*440)
        sh_ck[tid] = __fmul_rn(C32, (float)(tid + 1));
    }
    if (tid < NBATCH * 12) sh_par[tid] = g_params[tid];
    if (tid < NBATCH) sh_max[tid] = 0u;
    __syncthreads();

    int i = blockIdx.x * 256 + tid;
    bool act = (i < T_LEN);
    float fi = (float)i;
    const float DELTA = 4.0f / 176399.0f;   // compile-time IEEE f32
    float ti = __fmul_rn(fi, DELTA);        // jax linspace: iota * delta

    float acc[16];
#pragma unroll
    for (int b = 0; b < 16; b++) acc[b] = 0.0f;

#pragma unroll 4
    for (int k = 0; k < NHARM; k++) {
        float arg = __fmul_rn(sh_ck[k], ti);   // matches ref f32 rounding
        float sv = sin_fast(arg);
        const float4* hp = (const float4*)(sh_hd + k * 16);
        float4 h0 = hp[0], h1 = hp[1], h2 = hp[2], h3 = hp[3];
        acc[0]  = fmaf(h0.x, sv, acc[0]);  acc[1]  = fmaf(h0.y, sv, acc[1]);
        acc[2]  = fmaf(h0.z, sv, acc[2]);  acc[3]  = fmaf(h0.w, sv, acc[3]);
        acc[4]  = fmaf(h1.x, sv, acc[4]);  acc[5]  = fmaf(h1.y, sv, acc[5]);
        acc[6]  = fmaf(h1.z, sv, acc[6]);  acc[7]  = fmaf(h1.w, sv, acc[7]);
        acc[8]  = fmaf(h2.x, sv, acc[8]);  acc[9]  = fmaf(h2.y, sv, acc[9]);
        acc[10] = fmaf(h2.z, sv, acc[10]); acc[11] = fmaf(h2.w, sv, acc[11]);
        acc[12] = fmaf(h3.x, sv, acc[12]); acc[13] = fmaf(h3.y, sv, acc[13]);
        acc[14] = fmaf(h3.z, sv, acc[14]); acc[15] = fmaf(h3.w, sv, acc[15]);
    }

    const unsigned full = 0xFFFFFFFFu;
#pragma unroll
    for (int b = 0; b < 16; b++) {
        const float* P = sh_par + b * 12;
        float af = P[0], afd = P[1], ads = P[2];
        float ida = P[3], idd = P[4], idr = P[5];
        float sus = P[6], gn = P[7], nl = P[8];

        float env;
        if (fi < af)       env = fi * ida;
        else if (fi < afd) env = 1.0f + ((sus - 1.0f) * (fi - af)) * idd;
        else if (fi < ads) env = sus;
        else               env = sus * (1.0f - (fi - ads) * idr);

        float nz = act ? noise[b * T_LEN + i] : 0.0f;
        float nn = fmaf(nz, 2.0f, -1.0f) * nl;
        float sig = ((acc[b] + nn) * env) * gn;
        if (!act) sig = 0.0f;
        if (act) out[b * T_LEN + i] = sig;

        float am = fabsf(sig);
#pragma unroll
        for (int off = 16; off; off >>= 1)
            am = fmaxf(am, __shfl_xor_sync(full, am, off));
        if ((tid & 31) == 0) atomicMax(&sh_max[b], __float_as_uint(am));
    }
    __syncthreads();
    if (tid < NBATCH) atomicMax(&g_max[tid], sh_max[tid]);
}

// ---------------------------------------------------------------------------
// Kernel 3: normalize by per-batch max(|sig|)+1e-5  (float4 vectorized;
// T_LEN = 176400 = 44100 * 4)
// ---------------------------------------------------------------------------
__global__ void ddsp_norm(float4* __restrict__ out) {
    int i = blockIdx.x * 256 + threadIdx.x;
    int b = blockIdx.y;
    const int T4 = T_LEN / 4;
    if (i < T4) {
        float m = __uint_as_float(g_max[b]) + 1e-5f;
        float inv = 1.0f / m;
        float4 v = out[b * T4 + i];
        v.x *= inv; v.y *= inv; v.z *= inv; v.w *= inv;
        out[b * T4 + i] = v;
    }
}

extern "C" void kernel_launch(void* const* d_in, const int* in_sizes, int n_in,
                              void* d_out, int out_size) {
    // input order: base_audio, harmonic_dist, noise_bands, adsr, gain, noise
    const float* hd     = (const float*)d_in[1];
    const float* nbands = (const float*)d_in[2];
    const float* adsr   = (const float*)d_in[3];
    const float* gain   = (const float*)d_in[4];
    const float* noise  = (const float*)d_in[5];
    float* out = (float*)d_out;

    int grid = (T_LEN + 255) / 256;
    int grid4 = (T_LEN / 4 + 255) / 256;
    ddsp_prep<<<1, 32>>>(nbands, adsr, gain);
    ddsp_main<<<grid, 256>>>(hd, noise, out);
    ddsp_norm<<<dim3(grid4, NBATCH), 256>>>((float4*)out);
}